// round 4
// baseline (speedup 1.0000x reference)
#include <cuda_runtime.h>
#include <cstdint>

// Problem constants (fixed-shape problem: H=480, W=640, N=1e6)
#define HH 480
#define WW 640
#define HW (HH * WW)

// last-write-wins scatter scratch: (n+1)<<32 | float_bits(kp)
__device__ unsigned long long g_scratch[HW];

__global__ void zero_scratch_kernel() {
    int i = blockIdx.x * blockDim.x + threadIdx.x;
    if (i < HW) g_scratch[i] = 0ULL;
}

__global__ void finalize_depth_kernel(float* __restrict__ out) {
    int i = blockIdx.x * blockDim.x + threadIdx.x;
    if (i < HW) {
        unsigned long long p = g_scratch[i];
        out[i] = __uint_as_float((unsigned int)(p & 0xffffffffULL));
    }
}

// Bit-trick rsqrt + 2 Newton steps: pure FMA/ALU (avoids the quarter-rate MUFU
// pipe). Relative error ~1e-6; norm-type errors cancel in the final v2/v3 ratio.
__device__ __forceinline__ float frsqrt(float x) {
    float y = __uint_as_float(0x5f375a86u - (__float_as_uint(x) >> 1));
    float xh = 0.5f * x;
    y = y * (1.5f - xh * y * y);
    y = y * (1.5f - xh * y * y);
    return y;
}

__global__ void __launch_bounds__(256) triangulate_kernel(
    const float* __restrict__ T,      // [4,4]
    const float* __restrict__ K0,     // [3,3]
    const float* __restrict__ K1,     // [3,3]
    const float* __restrict__ mconf,  // [N]
    const float* __restrict__ kpts0,  // [N,2]
    const float* __restrict__ kpts1,  // [N,2]
    float* __restrict__ out,          // [HW + N]
    int n)
{
    int i = blockIdx.x * blockDim.x + threadIdx.x;
    if (i >= n) return;

    // ---- camera constants (broadcast loads, L1-resident) ----
    float fx0 = __ldg(K0 + 0), cx0 = __ldg(K0 + 2);
    float fy0 = __ldg(K0 + 4), cy0 = __ldg(K0 + 5);

    // P1 = K1 @ T[:3,:]  (3x4)
    float p1[3][4];
#pragma unroll
    for (int r = 0; r < 3; r++) {
        float k0c = __ldg(K1 + r * 3 + 0);
        float k1c = __ldg(K1 + r * 3 + 1);
        float k2c = __ldg(K1 + r * 3 + 2);
#pragma unroll
        for (int c = 0; c < 4; c++) {
            p1[r][c] = k0c * __ldg(T + 0 * 4 + c)
                     + k1c * __ldg(T + 1 * 4 + c)
                     + k2c * __ldg(T + 2 * 4 + c);
        }
    }

    // ---- per-point data (coalesced float2 loads) ----
    float2 pt0 = __ldg(((const float2*)kpts0) + i);
    float2 pt1 = __ldg(((const float2*)kpts1) + i);
    float m = __ldg(mconf + i);
    float x0 = pt0.x, y0 = pt0.y;
    float x1 = pt1.x, y1 = pt1.y;

    // ---- build A (4x4), stored as 4 COLUMNS a[col][row] ----
    // row0 = [-fx, 0, x0-cx, 0]          (conf 1)
    // row1 = [0, -fy, y0-cy, 0]
    // row2 = m*(x1*P1[2] - P1[0])
    // row3 = m*(y1*P1[2] - P1[1])
    float r2[4], r3[4];
#pragma unroll
    for (int j = 0; j < 4; j++) {
        r2[j] = m * (x1 * p1[2][j] - p1[0][j]);
        r3[j] = m * (y1 * p1[2][j] - p1[1][j]);
    }
    float a[4][4];
    a[0][0] = -fx0;      a[0][1] = 0.0f;      a[0][2] = r2[0]; a[0][3] = r3[0];
    a[1][0] = 0.0f;      a[1][1] = -fy0;      a[1][2] = r2[1]; a[1][3] = r3[1];
    a[2][0] = x0 - cx0;  a[2][1] = y0 - cy0;  a[2][2] = r2[2]; a[2][3] = r3[2];
    a[3][0] = 0.0f;      a[3][1] = 0.0f;      a[3][2] = r2[3]; a[3][3] = r3[3];

    // ---- one-sided Jacobi SVD on A (error ~ eps*kappa(A), not kappa^2).
    // Track only rows 2 and 3 of V (all the answer needs).
    float v2[4] = {0.0f, 0.0f, 1.0f, 0.0f};
    float v3[4] = {0.0f, 0.0f, 0.0f, 1.0f};

    const int PP[6] = {0, 0, 0, 1, 1, 2};
    const int QQ[6] = {1, 2, 3, 2, 3, 3};

#pragma unroll
    for (int sweep = 0; sweep < 5; sweep++) {
#pragma unroll
        for (int rr = 0; rr < 6; rr++) {
            const int p = PP[rr], q = QQ[rr];
            // Gram entries of column pair
            float al = 0.0f, be = 0.0f, g = 0.0f;
#pragma unroll
            for (int k = 0; k < 4; k++) {
                al = fmaf(a[p][k], a[p][k], al);
                be = fmaf(a[q][k], a[q][k], be);
                g  = fmaf(a[p][k], a[q][k], g);
            }
            // relative convergence test: skip already-orthogonal pairs
            if (g * g > 1e-14f * al * be) {
                // tan(2t) = 2g/(be-al), |t| <= pi/4. Two frsqrt, no divides.
                float d = be - al;
                float u = fmaf(d, d, 4.0f * g * g);
                float rsq = frsqrt(u);
                float cos2 = fabsf(d) * rsq;
                // sin2 = sign(d) * 2g/sqrt(u)  — keep sign of g AND d!
                float sin2 = copysignf(1.0f, d) * (2.0f * g * rsq);
                float w = 0.5f * (1.0f + cos2);
                float rw = frsqrt(w);
                float c = w * rw;            // sqrt(w) = cos(t)
                float s = 0.5f * sin2 * rw;  // sin2/(2c) = sin(t)
                // rotate columns p,q of A
#pragma unroll
                for (int k = 0; k < 4; k++) {
                    float ap = a[p][k], aq = a[q][k];
                    a[p][k] = c * ap - s * aq;
                    a[q][k] = s * ap + c * aq;
                }
                // rotate tracked V rows
                {
                    float t2p = v2[p], t2q = v2[q];
                    v2[p] = c * t2p - s * t2q;
                    v2[q] = s * t2p + c * t2q;
                    float t3p = v3[p], t3q = v3[q];
                    v3[p] = c * t3p - s * t3q;
                    v3[q] = s * t3p + c * t3q;
                }
            }
        }
    }

    // ---- column with smallest norm = smallest singular value ----
    int jmin = 0;
    float nmin = 3.4e38f;
#pragma unroll
    for (int j = 0; j < 4; j++) {
        float n2 = 0.0f;
#pragma unroll
        for (int k = 0; k < 4; k++) n2 = fmaf(a[j][k], a[j][k], n2);
        if (n2 < nmin) { nmin = n2; jmin = j; }
    }

    float z = __fdividef(v2[jmin], v3[jmin]);  // eigenvector sign cancels

    // clip like reference: [-1000,1000] then [0,30], then band filter
    z = fminf(fmaxf(z, -1000.0f), 1000.0f);
    float z2 = fminf(fmaxf(z, 0.0f), 30.0f);
    float kp = (z2 > 0.0f && z2 < 30.0f) ? z2 : 0.0f;

    out[HW + i] = kp;

    // ---- last-write-wins scatter (highest point index wins, like serial .set) ----
    int xi = (int)x0;
    int yi = (int)y0;
    unsigned long long packed =
        (((unsigned long long)(unsigned int)(i + 1)) << 32) |
        (unsigned long long)__float_as_uint(kp);
    atomicMax(&g_scratch[yi * WW + xi], packed);
}

extern "C" void kernel_launch(void* const* d_in, const int* in_sizes, int n_in,
                              void* d_out, int out_size) {
    // metadata order: T_0to1, K0, K1, mconf, mkpts0_f, mkpts1_f, image0, m_bids
    const float* T     = (const float*)d_in[0];
    const float* K0    = (const float*)d_in[1];
    const float* K1    = (const float*)d_in[2];
    const float* mconf = (const float*)d_in[3];
    const float* kp0   = (const float*)d_in[4];
    const float* kp1   = (const float*)d_in[5];
    float* out = (float*)d_out;
    int n = in_sizes[3];  // mconf element count = N

    const int T1 = 256;
    zero_scratch_kernel<<<(HW + T1 - 1) / T1, T1>>>();
    triangulate_kernel<<<(n + T1 - 1) / T1, T1>>>(T, K0, K1, mconf, kp0, kp1, out, n);
    finalize_depth_kernel<<<(HW + T1 - 1) / T1, T1>>>(out);
}